// round 12
// baseline (speedup 1.0000x reference)
#include <cuda_runtime.h>
#include <cuda_bf16.h>
#include <cstdint>
#include <cstddef>

// ---------------------------------------------------------------------------
// Problem constants
// ---------------------------------------------------------------------------
#define Bq   32
#define Tq   512
#define Dq   1024
#define Vq   256
#define Mq   (Bq * Tq)      // 16384 rows
#define G3   (3 * Dq)       // 3072 gate rows

// ---------------------------------------------------------------------------
// Scratch (static device arrays; no allocation allowed)
// ---------------------------------------------------------------------------
__device__ float g_act0[(size_t)Mq * Dq];          // 64 MB
__device__ float g_act1[(size_t)Mq * Dq];          // 64 MB
__device__ float g_xg[(size_t)Mq * G3];            // 192 MB (layer-1 gates)
__device__ float g_tab[(size_t)Vq * G3];           // 3 MB  (layer-0 gate table)
__device__ __nv_bfloat16 g_hhi[2][Bq * Dq];        // bf16 hi of h (dbl-buffered)
__device__ __nv_bfloat16 g_hlo[2][Bq * Dq];        // bf16 lo of h
__device__ int g_x_is64;

// ---------------------------------------------------------------------------
// GRU config: 128 CTAs x (8 dims -> 24 gate rows pad 32) x full K=1024.
// Warp = (rowgroup rg in {0,1}, k-quarter kq in {0..3}).  (R8 body)
// ---------------------------------------------------------------------------
#define GRU_NBLK    128
#define GRU_THREADS 256
#define ROWB        2064                 // 1024 bf16 + 8 pad = 2064 B row stride
#define SM_BLO_OFF  (32 * ROWB)          // 66048
#define SM_RED_OFF  (2 * 32 * ROWB)      // 132096
#define GRU_DYN_SMEM (SM_RED_OFF + 4 * 2 * 16 * 32 * 4 + 256)   // ~148.7 KB

// ---------------------------------------------------------------------------
// Dataflow sync state: per-CTA publish (slotP) + staged (slotC) gens,
// 256B apart (distinct L2 lines). Reset to 0 before each scan launch.
// ---------------------------------------------------------------------------
#define CPAD 64
__device__ unsigned g_slotP[GRU_NBLK * CPAD];
__device__ unsigned g_slotC[GRU_NBLK * CPAD];

// ---------------------------------------------------------------------------
// bf16 HMMA GEMM config (3-pass split): BM=128, BN=64, BK=64, 256 thr
// ---------------------------------------------------------------------------
#define GM_STRIDE  144                   // 64 bf16 = 128 B + 16 pad
#define GM_A_BYTES (128 * GM_STRIDE)     // 18432
#define GM_W_BYTES (64 * GM_STRIDE)      // 9216
#define GM_SMEM    (2 * GM_A_BYTES + 2 * GM_W_BYTES)   // 55296

__device__ __forceinline__ uint32_t smem_u32(const void *p) {
    uint32_t a;
    asm("{ .reg .u64 t; cvta.to.shared.u64 t, %1; cvt.u32.u64 %0, t; }"
        : "=r"(a) : "l"(p));
    return a;
}
__device__ __forceinline__ void ldmx4(uint32_t &r0, uint32_t &r1,
                                      uint32_t &r2, uint32_t &r3, uint32_t addr) {
    asm volatile("ldmatrix.sync.aligned.m8n8.x4.shared.b16 {%0,%1,%2,%3}, [%4];"
                 : "=r"(r0), "=r"(r1), "=r"(r2), "=r"(r3) : "r"(addr));
}
__device__ __forceinline__ void mma_bf16(float &c0, float &c1, float &c2, float &c3,
                                         uint32_t a0, uint32_t a1, uint32_t a2,
                                         uint32_t a3, uint32_t b0, uint32_t b1) {
    asm volatile(
        "mma.sync.aligned.m16n8k16.row.col.f32.bf16.bf16.f32 "
        "{%0,%1,%2,%3}, {%4,%5,%6,%7}, {%8,%9}, {%0,%1,%2,%3};"
        : "+f"(c0), "+f"(c1), "+f"(c2), "+f"(c3)
        : "r"(a0), "r"(a1), "r"(a2), "r"(a3), "r"(b0), "r"(b1));
}
__device__ __forceinline__ void split4(float4 v, uint2 &hi, uint2 &lo) {
    __nv_bfloat16 h0 = __float2bfloat16(v.x);
    __nv_bfloat16 h1 = __float2bfloat16(v.y);
    __nv_bfloat16 h2 = __float2bfloat16(v.z);
    __nv_bfloat16 h3 = __float2bfloat16(v.w);
    union { __nv_bfloat162 b[2]; uint2 u; } H, L;
    H.b[0] = __nv_bfloat162(h0, h1);
    H.b[1] = __nv_bfloat162(h2, h3);
    L.b[0] = __nv_bfloat162(__float2bfloat16(v.x - __bfloat162float(h0)),
                            __float2bfloat16(v.y - __bfloat162float(h1)));
    L.b[1] = __nv_bfloat162(__float2bfloat16(v.z - __bfloat162float(h2)),
                            __float2bfloat16(v.w - __bfloat162float(h3)));
    hi = H.u; lo = L.u;
}

__device__ __forceinline__ void st_rel(unsigned *p, unsigned v) {
    asm volatile("st.release.gpu.global.u32 [%0], %1;" :: "l"(p), "r"(v) : "memory");
}
__device__ __forceinline__ void wait_ge(const unsigned *p, unsigned tgt) {
    unsigned v;
    do {
        asm volatile("ld.acquire.gpu.global.u32 %0, [%1];"
                     : "=r"(v) : "l"(p) : "memory");
    } while ((int)(v - tgt) < 0);
}

// Stream-ordered slot reset (runs alone before each scan launch).
__global__ void bar_reset() {
    if (threadIdx.x < GRU_NBLK) {
        g_slotP[threadIdx.x * CPAD] = 0u;
        g_slotC[threadIdx.x * CPAD] = 0u;
    }
}

// ---------------------------------------------------------------------------
// int64-vs-int32 token dtype detection
// ---------------------------------------------------------------------------
__global__ void detect_kernel(const unsigned * __restrict__ xw) {
    if (threadIdx.x == 0 && blockIdx.x == 0) {
        int is64 = 1;
        for (int i = 1; i < 128; i += 2)
            if (xw[i] != 0u) { is64 = 0; break; }
        g_x_is64 = is64;
    }
}

// ---------------------------------------------------------------------------
// Split-bf16 (3-pass) HMMA NT GEMM: C[M,N] = A[M,K]*W[N,K]^T (+bias).
// (unchanged from R8 pass)
// ---------------------------------------------------------------------------
__global__ __launch_bounds__(256) void gemm_bf3(const float * __restrict__ A,
                                                const float * __restrict__ W,
                                                const float * __restrict__ bias,
                                                float * __restrict__ C,
                                                int M, int N, int K) {
    extern __shared__ char sm[];
    char *sAhi = sm;
    char *sAlo = sm + GM_A_BYTES;
    char *sWhi = sm + 2 * GM_A_BYTES;
    char *sWlo = sWhi + GM_W_BYTES;
    const uint32_t aHiA = smem_u32(sAhi);
    const uint32_t aLoA = smem_u32(sAlo);
    const uint32_t wHiA = smem_u32(sWhi);
    const uint32_t wLoA = smem_u32(sWlo);

    const int tid = threadIdx.x;
    const int lane = tid & 31;
    const int wid = tid >> 5;
    const int wm = wid & 3;
    const int wn = wid >> 2;
    const int bm = blockIdx.y * 128;
    const int bn = blockIdx.x * 64;

    float acc[2][4][4];
#pragma unroll
    for (int rg = 0; rg < 2; ++rg)
#pragma unroll
        for (int nt = 0; nt < 4; ++nt)
#pragma unroll
            for (int j = 0; j < 4; ++j) acc[rg][nt][j] = 0.f;

    const uint32_t aAddr = aHiA + (uint32_t)(wm * 32 + (lane & 15)) * GM_STRIDE
                         + (uint32_t)(lane >> 4) * 16;
    const uint32_t aLoOff = aLoA - aHiA;
    const int bRow = ((lane >> 4) & 1) * 8 + (lane & 7);
    const int bCol = ((lane >> 3) & 1) * 16;

    for (int k0 = 0; k0 < K; k0 += 64) {
        float4 av[8], wv[4];
#pragma unroll
        for (int j = 0; j < 8; ++j) {
            int idx = tid + j * 256, r = idx >> 4, c = idx & 15;
            av[j] = *(const float4 *)(A + (size_t)(bm + r) * K + k0 + c * 4);
        }
#pragma unroll
        for (int j = 0; j < 4; ++j) {
            int idx = tid + j * 256, r = idx >> 4, c = idx & 15;
            wv[j] = *(const float4 *)(W + (size_t)(bn + r) * K + k0 + c * 4);
        }
        __syncthreads();
#pragma unroll
        for (int j = 0; j < 8; ++j) {
            int idx = tid + j * 256, r = idx >> 4, c = idx & 15;
            uint2 hi, lo;
            split4(av[j], hi, lo);
            *(uint2 *)(sAhi + r * GM_STRIDE + c * 8) = hi;
            *(uint2 *)(sAlo + r * GM_STRIDE + c * 8) = lo;
        }
#pragma unroll
        for (int j = 0; j < 4; ++j) {
            int idx = tid + j * 256, r = idx >> 4, c = idx & 15;
            uint2 hi, lo;
            split4(wv[j], hi, lo);
            *(uint2 *)(sWhi + r * GM_STRIDE + c * 8) = hi;
            *(uint2 *)(sWlo + r * GM_STRIDE + c * 8) = lo;
        }
        __syncthreads();

        uint32_t aH[2][4][4], aL[2][4][4];
#pragma unroll
        for (int rg = 0; rg < 2; ++rg)
#pragma unroll
            for (int ks = 0; ks < 4; ++ks) {
                uint32_t ad = aAddr + (uint32_t)(rg * 16 * GM_STRIDE) + ks * 32;
                ldmx4(aH[rg][ks][0], aH[rg][ks][1], aH[rg][ks][2], aH[rg][ks][3], ad);
                ldmx4(aL[rg][ks][0], aL[rg][ks][1], aL[rg][ks][2], aL[rg][ks][3],
                      ad + aLoOff);
            }
#pragma unroll
        for (int ks = 0; ks < 4; ++ks) {
            uint32_t bh[8], bl[8];
#pragma unroll
            for (int pair = 0; pair < 2; ++pair) {
                uint32_t ba = (uint32_t)((wn * 32 + pair * 16 + bRow) * GM_STRIDE)
                            + bCol + ks * 32;
                ldmx4(bh[pair * 4 + 0], bh[pair * 4 + 1],
                      bh[pair * 4 + 2], bh[pair * 4 + 3], wHiA + ba);
                ldmx4(bl[pair * 4 + 0], bl[pair * 4 + 1],
                      bl[pair * 4 + 2], bl[pair * 4 + 3], wLoA + ba);
            }
#pragma unroll
            for (int rg = 0; rg < 2; ++rg)
#pragma unroll
                for (int nt = 0; nt < 4; ++nt) {
                    const int ib = nt * 2;
                    mma_bf16(acc[rg][nt][0], acc[rg][nt][1], acc[rg][nt][2], acc[rg][nt][3],
                             aH[rg][ks][0], aH[rg][ks][1], aH[rg][ks][2], aH[rg][ks][3],
                             bh[ib], bh[ib + 1]);
                    mma_bf16(acc[rg][nt][0], acc[rg][nt][1], acc[rg][nt][2], acc[rg][nt][3],
                             aH[rg][ks][0], aH[rg][ks][1], aH[rg][ks][2], aH[rg][ks][3],
                             bl[ib], bl[ib + 1]);
                    mma_bf16(acc[rg][nt][0], acc[rg][nt][1], acc[rg][nt][2], acc[rg][nt][3],
                             aL[rg][ks][0], aL[rg][ks][1], aL[rg][ks][2], aL[rg][ks][3],
                             bh[ib], bh[ib + 1]);
                }
        }
    }

    float b2x[4], b2y[4];
#pragma unroll
    for (int nt = 0; nt < 4; ++nt) {
        int col = bn + wn * 32 + nt * 8 + (lane & 3) * 2;
        b2x[nt] = bias ? __ldg(bias + col) : 0.f;
        b2y[nt] = bias ? __ldg(bias + col + 1) : 0.f;
    }
#pragma unroll
    for (int rg = 0; rg < 2; ++rg)
#pragma unroll
        for (int nt = 0; nt < 4; ++nt) {
            int row = bm + wm * 32 + rg * 16 + (lane >> 2);
            int col = bn + wn * 32 + nt * 8 + (lane & 3) * 2;
            float2 v0, v1;
            v0.x = acc[rg][nt][0] + b2x[nt];
            v0.y = acc[rg][nt][1] + b2y[nt];
            v1.x = acc[rg][nt][2] + b2x[nt];
            v1.y = acc[rg][nt][3] + b2y[nt];
            *(float2 *)(C + (size_t)row * N + col) = v0;
            *(float2 *)(C + (size_t)(row + 8) * N + col) = v1;
        }
}

// ---------------------------------------------------------------------------
// Persistent GRU scan, BARRIER-FREE dataflow sync.
// CTA blk owns dims d0 = blk*8 .. +8. Warp (rg,kq): rows rg*16..+16,
// K quarter kq*256..+256.
// Per step: warp waits only on its 32 producer CTAs (lane l <-> producer
// 32kq+l, acquire matches the exact data read), stages its 16-row slice,
// 2-warp named barrier, MMA. WAR on the h buffer is guarded by slotC
// (staged-gen), checked one step stale -> off critical path.
// ---------------------------------------------------------------------------
__global__ __launch_bounds__(GRU_THREADS, 1) void gru_mma(
        const float * __restrict__ Whh, const float * __restrict__ bhh,
        const float * __restrict__ xgv, const void * __restrict__ tokens,
        float * __restrict__ outp) {
    extern __shared__ char dynsm[];
    uint32_t raw = smem_u32(dynsm);
    uint32_t base = (raw + 127u) & ~127u;
    char *pb = dynsm + (base - raw);
    char *sB_hi = pb;
    char *sB_lo = pb + SM_BLO_OFF;
    float *red = (float *)(pb + SM_RED_OFF);       // [kq*2+rg][16][32]
    const uint32_t sBhiA = base, sBloA = base + SM_BLO_OFF;

    const int tid  = threadIdx.x;
    const int wid  = tid >> 5;
    const int lane = tid & 31;
    const int blk  = blockIdx.x;
    const int d0   = blk * 8;
    const int rg   = wid & 1;
    const int kq   = wid >> 1;

    // ---- prologue: split-bf16 weight fragments into registers ----
    uint32_t aH[16][4], aL[16][4];
    const uint32_t aAddr = sBhiA + (uint32_t)(rg * 16 + (lane & 15)) * ROWB
                         + (uint32_t)(lane >> 4) * 16 + (uint32_t)kq * 512;
#pragma unroll 1
    for (int pass = 0; pass < 2; ++pass) {
        for (int i = tid; i < 32 * 128; i += GRU_THREADS) {
            int row = i >> 7;          // 0..31
            int c = i & 127;           // 16B group (8 bf16)
            union { __nv_bfloat16 h[8]; uint4 u; } v;
            if (row < 24) {
                int g = row >> 3, dd = row & 7;
                const float *src = Whh + (size_t)(g * Dq + d0 + dd) * Dq + c * 8;
                float4 w0 = *(const float4 *)src;
                float4 w1 = *(const float4 *)(src + 4);
                float f[8] = {w0.x, w0.y, w0.z, w0.w, w1.x, w1.y, w1.z, w1.w};
#pragma unroll
                for (int j = 0; j < 8; ++j) {
                    __nv_bfloat16 hi = __float2bfloat16(f[j]);
                    v.h[j] = (pass == 0) ? hi
                           : __float2bfloat16(f[j] - __bfloat162float(hi));
                }
            } else {
                v.u = make_uint4(0u, 0u, 0u, 0u);
            }
            *(uint4 *)(sB_hi + row * ROWB + c * 16) = v.u;
        }
        __syncthreads();
        if (pass == 0) {
#pragma unroll
            for (int ks = 0; ks < 16; ++ks)
                ldmx4(aH[ks][0], aH[ks][1], aH[ks][2], aH[ks][3], aAddr + ks * 32);
        } else {
#pragma unroll
            for (int ks = 0; ks < 16; ++ks)
                ldmx4(aL[ks][0], aL[ks][1], aL[ks][2], aL[ks][3], aAddr + ks * 32);
        }
        __syncthreads();
    }

    // ---- zero OWN 8 columns of both h buffers, then publish h(0) ----
    for (int i = tid; i < 2 * 32 * 8; i += GRU_THREADS) {
        int buf = (i >= 256) ? 1 : 0;
        int j = i & 255;
        int b = j >> 3, dd = j & 7;
        g_hhi[buf][b * Dq + d0 + dd] = __float2bfloat16(0.f);
        g_hlo[buf][b * Dq + d0 + dd] = __float2bfloat16(0.f);
    }
    __syncthreads();
    if (tid == 0) st_rel(g_slotP + blk * CPAD, 1u);

    const int x64 = g_x_is64;

    // activation constants (thread -> (dd = tid>>5, b = tid&31))
    const int ab = tid & 31;
    const int ad = tid >> 5;
    const int dglob = d0 + ad;
    const float bh_r = __ldg(bhh + dglob);
    const float bh_z = __ldg(bhh + Dq + dglob);
    const float bh_n = __ldg(bhh + 2 * Dq + dglob);
    float hold = 0.f;

    // B ldmatrix lane pieces
    const int bRow = ((lane >> 4) & 1) * 8 + (lane & 7);
    const int bCol = ((lane >> 3) & 1) * 16;
    const uint32_t bBase = (uint32_t)kq * 512 + (uint32_t)bCol;

    // this lane's producer slot (matches exactly the columns it stages)
    const unsigned *myP = g_slotP + (kq * 32 + lane) * CPAD;

    for (unsigned t = 0; t < Tq; ++t) {
        const __nv_bfloat16 *hinH = g_hhi[t & 1];
        const __nv_bfloat16 *hinL = g_hlo[t & 1];
        __nv_bfloat16 *houtH = g_hhi[(t + 1) & 1];
        __nv_bfloat16 *houtL = g_hlo[(t + 1) & 1];

        // prefetch input gates early (independent of sync)
        float xr, xz, xn;
        {
            size_t xb;
            if (tokens) {
                int tok;
                if (x64) tok = (int)(((const long long *)tokens)[ab * Tq + t]);
                else     tok = ((const int *)tokens)[ab * Tq + t];
                xb = (size_t)tok * G3 + dglob;
            } else {
                xb = ((size_t)ab * Tq + t) * G3 + dglob;
            }
            xr = __ldg(xgv + xb);
            xz = __ldg(xgv + xb + Dq);
            xn = __ldg(xgv + xb + 2 * Dq);
        }

        // ---- wait for this lane's producer, then stage its columns ----
        wait_ge(myP, t + 1);
        // lane l reads ONLY producer (32kq+l)'s 8 columns; acquire pairs 1:1.
#pragma unroll
        for (int j = 0; j < 16; ++j) {
            const int row = rg * 16 + j;
            const size_t gs = (size_t)row * Dq + kq * 256 + lane * 8;
            uint4 vh = __ldcg((const uint4 *)(hinH + gs));
            uint4 vl = __ldcg((const uint4 *)(hinL + gs));
            char *db = sB_hi + row * ROWB + kq * 512 + lane * 16;
            *(uint4 *)(db) = vh;
            *(uint4 *)(db + SM_BLO_OFF) = vl;
        }
        // partner-warp sync for this quarter (both warps read all 32 rows)
        asm volatile("bar.sync %0, 64;" :: "r"(1 + kq) : "memory");

        // ---- per-warp 32x32x256 split-bf16 HMMA (3 passes) ----
        float acc[4][4];
#pragma unroll
        for (int nt = 0; nt < 4; ++nt)
#pragma unroll
            for (int j = 0; j < 4; ++j) acc[nt][j] = 0.f;

#pragma unroll
        for (int ks = 0; ks < 16; ++ks) {
            uint32_t bh[8], bl[8];
#pragma unroll
            for (int pair = 0; pair < 2; ++pair) {
                uint32_t ba = (uint32_t)((pair * 16 + bRow) * ROWB) + bBase + ks * 32;
                ldmx4(bh[pair * 4 + 0], bh[pair * 4 + 1],
                      bh[pair * 4 + 2], bh[pair * 4 + 3], sBhiA + ba);
                ldmx4(bl[pair * 4 + 0], bl[pair * 4 + 1],
                      bl[pair * 4 + 2], bl[pair * 4 + 3], sBloA + ba);
            }
#pragma unroll
            for (int nt = 0; nt < 4; ++nt) {
                const int ib = nt * 2;
                mma_bf16(acc[nt][0], acc[nt][1], acc[nt][2], acc[nt][3],
                         aH[ks][0], aH[ks][1], aH[ks][2], aH[ks][3],
                         bh[ib], bh[ib + 1]);
                mma_bf16(acc[nt][0], acc[nt][1], acc[nt][2], acc[nt][3],
                         aH[ks][0], aH[ks][1], aH[ks][2], aH[ks][3],
                         bl[ib], bl[ib + 1]);
                mma_bf16(acc[nt][0], acc[nt][1], acc[nt][2], acc[nt][3],
                         aL[ks][0], aL[ks][1], aL[ks][2], aL[ks][3],
                         bh[ib], bh[ib + 1]);
            }
        }

        // ---- intra-CTA k-reduction staging ----
        {
            float *rb = red + (size_t)((kq * 2 + rg) * 16 + (lane >> 2)) * 32;
#pragma unroll
            for (int nt = 0; nt < 4; ++nt) {
                const int b = nt * 8 + (lane & 3) * 2;
                float2 v0, v1;
                v0.x = acc[nt][0]; v0.y = acc[nt][1];
                v1.x = acc[nt][2]; v1.y = acc[nt][3];
                *(float2 *)(rb + b) = v0;
                *(float2 *)(rb + 8 * 32 + b) = v1;
            }
        }
        __syncthreads();

        // publish "staged step t"; wait all CTAs staged step t-1 (WAR guard,
        // one step stale -> normally satisfied on first poll)
        if (tid == 0) st_rel(g_slotC + blk * CPAD, t + 1);
        if (tid < GRU_NBLK) wait_ge(g_slotC + tid * CPAD, t);
        __syncthreads();

        // ---- fused activation (one elem per thread) ----
        {
            float hr = 0.f, hz = 0.f, hn = 0.f;
#pragma unroll
            for (int q = 0; q < 4; ++q) {
                hr += red[((q * 2 + 0) * 16 + ad) * 32 + ab];
                hz += red[((q * 2 + 0) * 16 + 8 + ad) * 32 + ab];
                hn += red[((q * 2 + 1) * 16 + ad) * 32 + ab];
            }
            hr += bh_r; hz += bh_z; hn += bh_n;
            float r = 1.f / (1.f + expf(-(xr + hr)));
            float z = 1.f / (1.f + expf(-(xz + hz)));
            float n = tanhf(xn + r * hn);
            float hnew = (1.f - z) * n + z * hold;
            hold = hnew;
            __nv_bfloat16 hh = __float2bfloat16(hnew);
            houtH[ab * Dq + dglob] = hh;
            houtL[ab * Dq + dglob] = __float2bfloat16(hnew - __bfloat162float(hh));
            outp[((size_t)ab * Tq + t) * Dq + dglob] = hnew;
        }
        __syncthreads();
        // publish h(t+1)
        if (tid == 0) st_rel(g_slotP + blk * CPAD, t + 2);
    }
}

// ---------------------------------------------------------------------------
// LayerNorm over last dim (1024), one block per row
// ---------------------------------------------------------------------------
__global__ __launch_bounds__(256) void ln_kernel(const float * __restrict__ in,
                                                 float * __restrict__ outp,
                                                 const float * __restrict__ gamma,
                                                 const float * __restrict__ beta) {
    __shared__ float red[2][8];
    const int row = blockIdx.x;
    const int tid = threadIdx.x;
    float4 x = *(const float4 *)&in[(size_t)row * Dq + tid * 4];
    float s = x.x + x.y + x.z + x.w;
    float q = x.x * x.x + x.y * x.y + x.z * x.z + x.w * x.w;
#pragma unroll
    for (int off = 16; off; off >>= 1) {
        s += __shfl_xor_sync(0xffffffffu, s, off);
        q += __shfl_xor_sync(0xffffffffu, q, off);
    }
    if ((tid & 31) == 0) { red[0][tid >> 5] = s; red[1][tid >> 5] = q; }
    __syncthreads();
    if (tid < 32) {
        float ss = (tid < 8) ? red[0][tid] : 0.f;
        float qq = (tid < 8) ? red[1][tid] : 0.f;
#pragma unroll
        for (int off = 4; off; off >>= 1) {
            ss += __shfl_xor_sync(0xffffffffu, ss, off);
            qq += __shfl_xor_sync(0xffffffffu, qq, off);
        }
        if (tid == 0) { red[0][0] = ss; red[1][0] = qq; }
    }
    __syncthreads();
    const float mean = red[0][0] * (1.f / Dq);
    const float var = red[1][0] * (1.f / Dq) - mean * mean;
    const float inv = rsqrtf(var + 1e-5f);
    float4 g  = *(const float4 *)&gamma[tid * 4];
    float4 be = *(const float4 *)&beta[tid * 4];
    float4 o;
    o.x = (x.x - mean) * inv * g.x + be.x;
    o.y = (x.y - mean) * inv * g.y + be.y;
    o.z = (x.z - mean) * inv * g.z + be.z;
    o.w = (x.w - mean) * inv * g.w + be.w;
    *(float4 *)&outp[(size_t)row * Dq + tid * 4] = o;
}

// ---------------------------------------------------------------------------
// Host driver. Inputs: x, E, Wih, Whh, bih, bhh, gamma, beta. Output f32.
// ---------------------------------------------------------------------------
extern "C" void kernel_launch(void *const *d_in, const int *in_sizes, int n_in,
                              void *d_out, int out_size) {
    (void)in_sizes; (void)n_in; (void)out_size;
    const void  *x     = d_in[0];
    const float *E     = (const float *)d_in[1];
    const float *Wih   = (const float *)d_in[2];
    const float *Whh   = (const float *)d_in[3];
    const float *bih   = (const float *)d_in[4];
    const float *bhh   = (const float *)d_in[5];
    const float *gamma = (const float *)d_in[6];
    const float *beta  = (const float *)d_in[7];
    float *out = (float *)d_out;

    float *act0 = nullptr, *act1 = nullptr, *xg = nullptr, *tab = nullptr;
    cudaGetSymbolAddress((void **)&act0, g_act0);
    cudaGetSymbolAddress((void **)&act1, g_act1);
    cudaGetSymbolAddress((void **)&xg, g_xg);
    cudaGetSymbolAddress((void **)&tab, g_tab);

    cudaFuncSetAttribute(gru_mma, cudaFuncAttributeMaxDynamicSharedMemorySize,
                         GRU_DYN_SMEM);
    cudaFuncSetAttribute(gemm_bf3, cudaFuncAttributeMaxDynamicSharedMemorySize,
                         GM_SMEM);

    detect_kernel<<<1, 32>>>((const unsigned *)x);

    // layer 0: per-vocab gate table + tensor-core scan
    {
        dim3 gt(G3 / 64, Vq / 128);
        gemm_bf3<<<gt, 256, GM_SMEM>>>(E, Wih, bih, tab, Vq, G3, Dq);
    }
    bar_reset<<<1, GRU_NBLK>>>();
    gru_mma<<<GRU_NBLK, GRU_THREADS, GRU_DYN_SMEM>>>(Whh, bhh, tab, x, act1);

    // layer 1: dense input-gate GEMM (bf16 HMMA) + tensor-core scan
    {
        dim3 gx(G3 / 64, Mq / 128);
        gemm_bf3<<<gx, 256, GM_SMEM>>>(act1, Wih + (size_t)G3 * Dq, bih + G3,
                                       xg, Mq, G3, Dq);
    }
    bar_reset<<<1, GRU_NBLK>>>();
    gru_mma<<<GRU_NBLK, GRU_THREADS, GRU_DYN_SMEM>>>(Whh + (size_t)G3 * Dq,
                                                     bhh + G3, xg, nullptr, act0);

    // LayerNorm + tied head (bf16 HMMA)
    ln_kernel<<<Mq, 256>>>(act0, act1, gamma, beta);
    dim3 gh(Vq / 64, Mq / 128);
    gemm_bf3<<<gh, 256, GM_SMEM>>>(act1, E, nullptr, out, Mq, Vq, Dq);
}

// round 14
// speedup vs baseline: 1.1100x; 1.1100x over previous
#include <cuda_runtime.h>
#include <cuda_bf16.h>
#include <cstdint>
#include <cstddef>

// ---------------------------------------------------------------------------
// Problem constants
// ---------------------------------------------------------------------------
#define Bq   32
#define Tq   512
#define Dq   1024
#define Vq   256
#define Mq   (Bq * Tq)      // 16384 rows
#define G3   (3 * Dq)       // 3072 gate rows

// ---------------------------------------------------------------------------
// Scratch (static device arrays; no allocation allowed)
// ---------------------------------------------------------------------------
__device__ float g_act0[(size_t)Mq * Dq];          // 64 MB
__device__ float g_act1[(size_t)Mq * Dq];          // 64 MB
__device__ float g_xg[(size_t)Mq * G3];            // 192 MB (layer-1 gates)
__device__ float g_tab[(size_t)Vq * G3];           // 3 MB  (layer-0 gate table)
__device__ __nv_bfloat16 g_hhi[2][Bq * Dq];        // bf16 hi of h (dbl-buffered)
__device__ __nv_bfloat16 g_hlo[2][Bq * Dq];        // bf16 lo of h
__device__ int g_x_is64;

// ---------------------------------------------------------------------------
// GRU config: 128 CTAs x (8 dims -> 24 gate rows pad 32) x full K=1024.
// Warp = (rowgroup rg in {0,1}, k-quarter kq in {0..3}).  (R8 body)
// ---------------------------------------------------------------------------
#define GRU_NBLK    128
#define GRU_THREADS 256
#define ROWB        2064                 // 1024 bf16 + 8 pad = 2064 B row stride
#define SM_BLO_OFF  (32 * ROWB)          // 66048
#define SM_RED_OFF  (2 * 32 * ROWB)      // 132096
#define GRU_DYN_SMEM (SM_RED_OFF + 4 * 2 * 16 * 32 * 4 + 256)   // ~148.7 KB

// ---------------------------------------------------------------------------
// Barrier state: one arrival slot per CTA, 256B apart (distinct L2 lines).
// Single-writer slots; reset to 0 by bar_reset before each scan launch.
// ---------------------------------------------------------------------------
#define CPAD 64
__device__ unsigned g_slot[GRU_NBLK * CPAD];

// ---------------------------------------------------------------------------
// bf16 HMMA GEMM config (3-pass split): BM=128, BN=64, BK=64, 256 thr
// ---------------------------------------------------------------------------
#define GM_STRIDE  144                   // 64 bf16 = 128 B + 16 pad
#define GM_A_BYTES (128 * GM_STRIDE)     // 18432
#define GM_W_BYTES (64 * GM_STRIDE)      // 9216
#define GM_SMEM    (2 * GM_A_BYTES + 2 * GM_W_BYTES)   // 55296

__device__ __forceinline__ uint32_t smem_u32(const void *p) {
    uint32_t a;
    asm("{ .reg .u64 t; cvta.to.shared.u64 t, %1; cvt.u32.u64 %0, t; }"
        : "=r"(a) : "l"(p));
    return a;
}
__device__ __forceinline__ void ldmx4(uint32_t &r0, uint32_t &r1,
                                      uint32_t &r2, uint32_t &r3, uint32_t addr) {
    asm volatile("ldmatrix.sync.aligned.m8n8.x4.shared.b16 {%0,%1,%2,%3}, [%4];"
                 : "=r"(r0), "=r"(r1), "=r"(r2), "=r"(r3) : "r"(addr));
}
__device__ __forceinline__ void mma_bf16(float &c0, float &c1, float &c2, float &c3,
                                         uint32_t a0, uint32_t a1, uint32_t a2,
                                         uint32_t a3, uint32_t b0, uint32_t b1) {
    asm volatile(
        "mma.sync.aligned.m16n8k16.row.col.f32.bf16.bf16.f32 "
        "{%0,%1,%2,%3}, {%4,%5,%6,%7}, {%8,%9}, {%0,%1,%2,%3};"
        : "+f"(c0), "+f"(c1), "+f"(c2), "+f"(c3)
        : "r"(a0), "r"(a1), "r"(a2), "r"(a3), "r"(b0), "r"(b1));
}
__device__ __forceinline__ void split4(float4 v, uint2 &hi, uint2 &lo) {
    __nv_bfloat16 h0 = __float2bfloat16(v.x);
    __nv_bfloat16 h1 = __float2bfloat16(v.y);
    __nv_bfloat16 h2 = __float2bfloat16(v.z);
    __nv_bfloat16 h3 = __float2bfloat16(v.w);
    union { __nv_bfloat162 b[2]; uint2 u; } H, L;
    H.b[0] = __nv_bfloat162(h0, h1);
    H.b[1] = __nv_bfloat162(h2, h3);
    L.b[0] = __nv_bfloat162(__float2bfloat16(v.x - __bfloat162float(h0)),
                            __float2bfloat16(v.y - __bfloat162float(h1)));
    L.b[1] = __nv_bfloat162(__float2bfloat16(v.z - __bfloat162float(h2)),
                            __float2bfloat16(v.w - __bfloat162float(h3)));
    hi = H.u; lo = L.u;
}

// ---------------------------------------------------------------------------
// Grid barrier v3: one-hop all-to-all. (R11, proven)
// ---------------------------------------------------------------------------
__device__ __forceinline__ void gbar(int blk, int tid, unsigned &gen) {
    gen += 1u;
    __syncthreads();
    if (tid == 0)
        asm volatile("st.release.gpu.global.u32 [%0], %1;"
                     :: "l"(g_slot + blk * CPAD), "r"(gen) : "memory");
    if (tid < GRU_NBLK) {
        unsigned v;
        do {
            asm volatile("ld.acquire.gpu.global.u32 %0, [%1];"
                         : "=r"(v) : "l"(g_slot + tid * CPAD) : "memory");
        } while ((int)(v - gen) < 0);
    }
    __syncthreads();
}

// Stream-ordered slot reset (runs alone before each scan launch).
__global__ void bar_reset() {
    if (threadIdx.x < GRU_NBLK) g_slot[threadIdx.x * CPAD] = 0u;
}

// ---------------------------------------------------------------------------
// int64-vs-int32 token dtype detection
// ---------------------------------------------------------------------------
__global__ void detect_kernel(const unsigned * __restrict__ xw) {
    if (threadIdx.x == 0 && blockIdx.x == 0) {
        int is64 = 1;
        for (int i = 1; i < 128; i += 2)
            if (xw[i] != 0u) { is64 = 0; break; }
        g_x_is64 = is64;
    }
}

// ---------------------------------------------------------------------------
// Split-bf16 (3-pass) HMMA NT GEMM, software-pipelined k-loop:
// global loads for iter k+1 issue right after the store-sync of iter k and
// overlap the entire ldsm/MMA block. Arithmetic bit-identical to R8/R11.
// ---------------------------------------------------------------------------
__global__ __launch_bounds__(256) void gemm_bf3(const float * __restrict__ A,
                                                const float * __restrict__ W,
                                                const float * __restrict__ bias,
                                                float * __restrict__ C,
                                                int M, int N, int K) {
    extern __shared__ char sm[];
    char *sAhi = sm;
    char *sAlo = sm + GM_A_BYTES;
    char *sWhi = sm + 2 * GM_A_BYTES;
    char *sWlo = sWhi + GM_W_BYTES;
    const uint32_t aHiA = smem_u32(sAhi);
    const uint32_t aLoA = smem_u32(sAlo);
    const uint32_t wHiA = smem_u32(sWhi);
    const uint32_t wLoA = smem_u32(sWlo);

    const int tid = threadIdx.x;
    const int lane = tid & 31;
    const int wid = tid >> 5;
    const int wm = wid & 3;
    const int wn = wid >> 2;
    const int bm = blockIdx.y * 128;
    const int bn = blockIdx.x * 64;

    float acc[2][4][4];
#pragma unroll
    for (int rg = 0; rg < 2; ++rg)
#pragma unroll
        for (int nt = 0; nt < 4; ++nt)
#pragma unroll
            for (int j = 0; j < 4; ++j) acc[rg][nt][j] = 0.f;

    const uint32_t aAddr = aHiA + (uint32_t)(wm * 32 + (lane & 15)) * GM_STRIDE
                         + (uint32_t)(lane >> 4) * 16;
    const uint32_t aLoOff = aLoA - aHiA;
    const int bRow = ((lane >> 4) & 1) * 8 + (lane & 7);
    const int bCol = ((lane >> 3) & 1) * 16;

    const int ar = tid >> 4, ac = (tid & 15) * 4;   // loader row/col pieces

    // prologue: load k0 = 0
    float4 av[8], wv[4];
#pragma unroll
    for (int j = 0; j < 8; ++j)
        av[j] = *(const float4 *)(A + (size_t)(bm + ar + j * 16) * K + ac);
#pragma unroll
    for (int j = 0; j < 4; ++j)
        wv[j] = *(const float4 *)(W + (size_t)(bn + ar + j * 16) * K + ac);

    for (int k0 = 0; k0 < K; k0 += 64) {
        __syncthreads();
#pragma unroll
        for (int j = 0; j < 8; ++j) {
            uint2 hi, lo;
            split4(av[j], hi, lo);
            *(uint2 *)(sAhi + (ar + j * 16) * GM_STRIDE + (ac >> 2) * 8) = hi;
            *(uint2 *)(sAlo + (ar + j * 16) * GM_STRIDE + (ac >> 2) * 8) = lo;
        }
#pragma unroll
        for (int j = 0; j < 4; ++j) {
            uint2 hi, lo;
            split4(wv[j], hi, lo);
            *(uint2 *)(sWhi + (ar + j * 16) * GM_STRIDE + (ac >> 2) * 8) = hi;
            *(uint2 *)(sWlo + (ar + j * 16) * GM_STRIDE + (ac >> 2) * 8) = lo;
        }
        __syncthreads();

        // prefetch next chunk (overlaps the MMA block below)
        if (k0 + 64 < K) {
#pragma unroll
            for (int j = 0; j < 8; ++j)
                av[j] = *(const float4 *)(A + (size_t)(bm + ar + j * 16) * K
                                          + k0 + 64 + ac);
#pragma unroll
            for (int j = 0; j < 4; ++j)
                wv[j] = *(const float4 *)(W + (size_t)(bn + ar + j * 16) * K
                                          + k0 + 64 + ac);
        }

        uint32_t aH[2][4][4], aL[2][4][4];
#pragma unroll
        for (int rg = 0; rg < 2; ++rg)
#pragma unroll
            for (int ks = 0; ks < 4; ++ks) {
                uint32_t ad = aAddr + (uint32_t)(rg * 16 * GM_STRIDE) + ks * 32;
                ldmx4(aH[rg][ks][0], aH[rg][ks][1], aH[rg][ks][2], aH[rg][ks][3], ad);
                ldmx4(aL[rg][ks][0], aL[rg][ks][1], aL[rg][ks][2], aL[rg][ks][3],
                      ad + aLoOff);
            }
#pragma unroll
        for (int ks = 0; ks < 4; ++ks) {
            uint32_t bh[8], bl[8];
#pragma unroll
            for (int pair = 0; pair < 2; ++pair) {
                uint32_t ba = (uint32_t)((wn * 32 + pair * 16 + bRow) * GM_STRIDE)
                            + bCol + ks * 32;
                ldmx4(bh[pair * 4 + 0], bh[pair * 4 + 1],
                      bh[pair * 4 + 2], bh[pair * 4 + 3], wHiA + ba);
                ldmx4(bl[pair * 4 + 0], bl[pair * 4 + 1],
                      bl[pair * 4 + 2], bl[pair * 4 + 3], wLoA + ba);
            }
#pragma unroll
            for (int rg = 0; rg < 2; ++rg)
#pragma unroll
                for (int nt = 0; nt < 4; ++nt) {
                    const int ib = nt * 2;
                    mma_bf16(acc[rg][nt][0], acc[rg][nt][1], acc[rg][nt][2], acc[rg][nt][3],
                             aH[rg][ks][0], aH[rg][ks][1], aH[rg][ks][2], aH[rg][ks][3],
                             bh[ib], bh[ib + 1]);
                    mma_bf16(acc[rg][nt][0], acc[rg][nt][1], acc[rg][nt][2], acc[rg][nt][3],
                             aH[rg][ks][0], aH[rg][ks][1], aH[rg][ks][2], aH[rg][ks][3],
                             bl[ib], bl[ib + 1]);
                    mma_bf16(acc[rg][nt][0], acc[rg][nt][1], acc[rg][nt][2], acc[rg][nt][3],
                             aL[rg][ks][0], aL[rg][ks][1], aL[rg][ks][2], aL[rg][ks][3],
                             bh[ib], bh[ib + 1]);
                }
        }
    }

    float b2x[4], b2y[4];
#pragma unroll
    for (int nt = 0; nt < 4; ++nt) {
        int col = bn + wn * 32 + nt * 8 + (lane & 3) * 2;
        b2x[nt] = bias ? __ldg(bias + col) : 0.f;
        b2y[nt] = bias ? __ldg(bias + col + 1) : 0.f;
    }
#pragma unroll
    for (int rg = 0; rg < 2; ++rg)
#pragma unroll
        for (int nt = 0; nt < 4; ++nt) {
            int row = bm + wm * 32 + rg * 16 + (lane >> 2);
            int col = bn + wn * 32 + nt * 8 + (lane & 3) * 2;
            float2 v0, v1;
            v0.x = acc[rg][nt][0] + b2x[nt];
            v0.y = acc[rg][nt][1] + b2y[nt];
            v1.x = acc[rg][nt][2] + b2x[nt];
            v1.y = acc[rg][nt][3] + b2y[nt];
            *(float2 *)(C + (size_t)row * N + col) = v0;
            *(float2 *)(C + (size_t)(row + 8) * N + col) = v1;
        }
}

// ---------------------------------------------------------------------------
// Persistent GRU scan, one grid barrier per step (R11 body, byte-identical).
// ---------------------------------------------------------------------------
__global__ __launch_bounds__(GRU_THREADS, 1) void gru_mma(
        const float * __restrict__ Whh, const float * __restrict__ bhh,
        const float * __restrict__ xgv, const void * __restrict__ tokens,
        float * __restrict__ outp) {
    extern __shared__ char dynsm[];
    uint32_t raw = smem_u32(dynsm);
    uint32_t base = (raw + 127u) & ~127u;
    char *pb = dynsm + (base - raw);
    char *sB_hi = pb;
    char *sB_lo = pb + SM_BLO_OFF;
    float *red = (float *)(pb + SM_RED_OFF);       // [kq*2+rg][16][32]
    const uint32_t sBhiA = base, sBloA = base + SM_BLO_OFF;

    const int tid  = threadIdx.x;
    const int wid  = tid >> 5;
    const int lane = tid & 31;
    const int blk  = blockIdx.x;
    const int d0   = blk * 8;
    const int rg   = wid & 1;
    const int kq   = wid >> 1;

    // ---- prologue: split-bf16 weight fragments into registers ----
    uint32_t aH[16][4], aL[16][4];
    const uint32_t aAddr = sBhiA + (uint32_t)(rg * 16 + (lane & 15)) * ROWB
                         + (uint32_t)(lane >> 4) * 16 + (uint32_t)kq * 512;
#pragma unroll 1
    for (int pass = 0; pass < 2; ++pass) {
        for (int i = tid; i < 32 * 128; i += GRU_THREADS) {
            int row = i >> 7;          // 0..31
            int c = i & 127;           // 16B group (8 bf16)
            union { __nv_bfloat16 h[8]; uint4 u; } v;
            if (row < 24) {
                int g = row >> 3, dd = row & 7;
                const float *src = Whh + (size_t)(g * Dq + d0 + dd) * Dq + c * 8;
                float4 w0 = *(const float4 *)src;
                float4 w1 = *(const float4 *)(src + 4);
                float f[8] = {w0.x, w0.y, w0.z, w0.w, w1.x, w1.y, w1.z, w1.w};
#pragma unroll
                for (int j = 0; j < 8; ++j) {
                    __nv_bfloat16 hi = __float2bfloat16(f[j]);
                    v.h[j] = (pass == 0) ? hi
                           : __float2bfloat16(f[j] - __bfloat162float(hi));
                }
            } else {
                v.u = make_uint4(0u, 0u, 0u, 0u);
            }
            *(uint4 *)(sB_hi + row * ROWB + c * 16) = v.u;
        }
        __syncthreads();
        if (pass == 0) {
#pragma unroll
            for (int ks = 0; ks < 16; ++ks)
                ldmx4(aH[ks][0], aH[ks][1], aH[ks][2], aH[ks][3], aAddr + ks * 32);
        } else {
#pragma unroll
            for (int ks = 0; ks < 16; ++ks)
                ldmx4(aL[ks][0], aL[ks][1], aL[ks][2], aL[ks][3], aAddr + ks * 32);
        }
        __syncthreads();
    }

    // zero both h buffers
    for (int i = blk * GRU_THREADS + tid; i < 2 * Bq * Dq;
         i += GRU_NBLK * GRU_THREADS) {
        ((__nv_bfloat16 *)g_hhi)[i] = __float2bfloat16(0.f);
        ((__nv_bfloat16 *)g_hlo)[i] = __float2bfloat16(0.f);
    }

    unsigned gen = 0;                  // slots zeroed by bar_reset
    gbar(blk, tid, gen);
    const int x64 = g_x_is64;

    // activation constants (thread -> (dd = tid>>5, b = tid&31))
    const int ab = tid & 31;
    const int ad = tid >> 5;
    const int dglob = d0 + ad;
    const float bh_r = __ldg(bhh + dglob);
    const float bh_z = __ldg(bhh + Dq + dglob);
    const float bh_n = __ldg(bhh + 2 * Dq + dglob);
    float hold = 0.f;

    // B ldmatrix lane pieces
    const int bRow = ((lane >> 4) & 1) * 8 + (lane & 7);
    const int bCol = ((lane >> 3) & 1) * 16;
    const uint32_t bBase = (uint32_t)kq * 512 + (uint32_t)bCol;

    for (int t = 0; t < Tq; ++t) {
        const __nv_bfloat16 *hinH = g_hhi[t & 1];
        const __nv_bfloat16 *hinL = g_hlo[t & 1];
        __nv_bfloat16 *houtH = g_hhi[(t + 1) & 1];
        __nv_bfloat16 *houtL = g_hlo[(t + 1) & 1];

        // prefetch input gates early (hidden under staging + MMA)
        float xr, xz, xn;
        {
            size_t xb;
            if (tokens) {
                int tok;
                if (x64) tok = (int)(((const long long *)tokens)[ab * Tq + t]);
                else     tok = ((const int *)tokens)[ab * Tq + t];
                xb = (size_t)tok * G3 + dglob;
            } else {
                xb = ((size_t)ab * Tq + t) * G3 + dglob;
            }
            xr = __ldg(xgv + xb);
            xz = __ldg(xgv + xb + Dq);
            xn = __ldg(xgv + xb + 2 * Dq);
        }

        // ---- stage full h (bf16 hi/lo) into smem ----
#pragma unroll
        for (int j = 0; j < 16; ++j) {
            int idx = tid + j * GRU_THREADS;     // 0..4095
            int row = idx >> 7;
            int c = idx & 127;
            uint4 vh = __ldcg((const uint4 *)(hinH + row * Dq + c * 8));
            uint4 vl = __ldcg((const uint4 *)(hinL + row * Dq + c * 8));
            *(uint4 *)(sB_hi + row * ROWB + c * 16) = vh;
            *(uint4 *)(sB_lo + row * ROWB + c * 16) = vl;
        }
        __syncthreads();

        // ---- per-warp 32x32x256 split-bf16 HMMA (3 passes) ----
        float acc[4][4];
#pragma unroll
        for (int nt = 0; nt < 4; ++nt)
#pragma unroll
            for (int j = 0; j < 4; ++j) acc[nt][j] = 0.f;

#pragma unroll
        for (int ks = 0; ks < 16; ++ks) {
            uint32_t bh[8], bl[8];
#pragma unroll
            for (int pair = 0; pair < 2; ++pair) {
                uint32_t ba = (uint32_t)((pair * 16 + bRow) * ROWB) + bBase + ks * 32;
                ldmx4(bh[pair * 4 + 0], bh[pair * 4 + 1],
                      bh[pair * 4 + 2], bh[pair * 4 + 3], sBhiA + ba);
                ldmx4(bl[pair * 4 + 0], bl[pair * 4 + 1],
                      bl[pair * 4 + 2], bl[pair * 4 + 3], sBloA + ba);
            }
#pragma unroll
            for (int nt = 0; nt < 4; ++nt) {
                const int ib = nt * 2;
                mma_bf16(acc[nt][0], acc[nt][1], acc[nt][2], acc[nt][3],
                         aH[ks][0], aH[ks][1], aH[ks][2], aH[ks][3],
                         bh[ib], bh[ib + 1]);
                mma_bf16(acc[nt][0], acc[nt][1], acc[nt][2], acc[nt][3],
                         aH[ks][0], aH[ks][1], aH[ks][2], aH[ks][3],
                         bl[ib], bl[ib + 1]);
                mma_bf16(acc[nt][0], acc[nt][1], acc[nt][2], acc[nt][3],
                         aL[ks][0], aL[ks][1], aL[ks][2], aL[ks][3],
                         bh[ib], bh[ib + 1]);
            }
        }

        // ---- intra-CTA k-reduction staging ----
        {
            float *rb = red + (size_t)((kq * 2 + rg) * 16 + (lane >> 2)) * 32;
#pragma unroll
            for (int nt = 0; nt < 4; ++nt) {
                const int b = nt * 8 + (lane & 3) * 2;
                float2 v0, v1;
                v0.x = acc[nt][0]; v0.y = acc[nt][1];
                v1.x = acc[nt][2]; v1.y = acc[nt][3];
                *(float2 *)(rb + b) = v0;
                *(float2 *)(rb + 8 * 32 + b) = v1;
            }
        }
        __syncthreads();

        // ---- fused activation (one elem per thread) ----
        {
            float hr = 0.f, hz = 0.f, hn = 0.f;
#pragma unroll
            for (int q = 0; q < 4; ++q) {
                hr += red[((q * 2 + 0) * 16 + ad) * 32 + ab];
                hz += red[((q * 2 + 0) * 16 + 8 + ad) * 32 + ab];
                hn += red[((q * 2 + 1) * 16 + ad) * 32 + ab];
            }
            hr += bh_r; hz += bh_z; hn += bh_n;
            float r = 1.f / (1.f + expf(-(xr + hr)));
            float z = 1.f / (1.f + expf(-(xz + hz)));
            float n = tanhf(xn + r * hn);
            float hnew = (1.f - z) * n + z * hold;
            hold = hnew;
            __nv_bfloat16 hh = __float2bfloat16(hnew);
            houtH[ab * Dq + dglob] = hh;
            houtL[ab * Dq + dglob] = __float2bfloat16(hnew - __bfloat162float(hh));
            outp[((size_t)ab * Tq + t) * Dq + dglob] = hnew;
        }
        gbar(blk, tid, gen);
    }
}

// ---------------------------------------------------------------------------
// LayerNorm over last dim (1024), one block per row
// ---------------------------------------------------------------------------
__global__ __launch_bounds__(256) void ln_kernel(const float * __restrict__ in,
                                                 float * __restrict__ outp,
                                                 const float * __restrict__ gamma,
                                                 const float * __restrict__ beta) {
    __shared__ float red[2][8];
    const int row = blockIdx.x;
    const int tid = threadIdx.x;
    float4 x = *(const float4 *)&in[(size_t)row * Dq + tid * 4];
    float s = x.x + x.y + x.z + x.w;
    float q = x.x * x.x + x.y * x.y + x.z * x.z + x.w * x.w;
#pragma unroll
    for (int off = 16; off; off >>= 1) {
        s += __shfl_xor_sync(0xffffffffu, s, off);
        q += __shfl_xor_sync(0xffffffffu, q, off);
    }
    if ((tid & 31) == 0) { red[0][tid >> 5] = s; red[1][tid >> 5] = q; }
    __syncthreads();
    if (tid < 32) {
        float ss = (tid < 8) ? red[0][tid] : 0.f;
        float qq = (tid < 8) ? red[1][tid] : 0.f;
#pragma unroll
        for (int off = 4; off; off >>= 1) {
            ss += __shfl_xor_sync(0xffffffffu, ss, off);
            qq += __shfl_xor_sync(0xffffffffu, qq, off);
        }
        if (tid == 0) { red[0][0] = ss; red[1][0] = qq; }
    }
    __syncthreads();
    const float mean = red[0][0] * (1.f / Dq);
    const float var = red[1][0] * (1.f / Dq) - mean * mean;
    const float inv = rsqrtf(var + 1e-5f);
    float4 g  = *(const float4 *)&gamma[tid * 4];
    float4 be = *(const float4 *)&beta[tid * 4];
    float4 o;
    o.x = (x.x - mean) * inv * g.x + be.x;
    o.y = (x.y - mean) * inv * g.y + be.y;
    o.z = (x.z - mean) * inv * g.z + be.z;
    o.w = (x.w - mean) * inv * g.w + be.w;
    *(float4 *)&outp[(size_t)row * Dq + tid * 4] = o;
}

// ---------------------------------------------------------------------------
// Host driver. Inputs: x, E, Wih, Whh, bih, bhh, gamma, beta. Output f32.
// ---------------------------------------------------------------------------
extern "C" void kernel_launch(void *const *d_in, const int *in_sizes, int n_in,
                              void *d_out, int out_size) {
    (void)in_sizes; (void)n_in; (void)out_size;
    const void  *x     = d_in[0];
    const float *E     = (const float *)d_in[1];
    const float *Wih   = (const float *)d_in[2];
    const float *Whh   = (const float *)d_in[3];
    const float *bih   = (const float *)d_in[4];
    const float *bhh   = (const float *)d_in[5];
    const float *gamma = (const float *)d_in[6];
    const float *beta  = (const float *)d_in[7];
    float *out = (float *)d_out;

    float *act0 = nullptr, *act1 = nullptr, *xg = nullptr, *tab = nullptr;
    cudaGetSymbolAddress((void **)&act0, g_act0);
    cudaGetSymbolAddress((void **)&act1, g_act1);
    cudaGetSymbolAddress((void **)&xg, g_xg);
    cudaGetSymbolAddress((void **)&tab, g_tab);

    cudaFuncSetAttribute(gru_mma, cudaFuncAttributeMaxDynamicSharedMemorySize,
                         GRU_DYN_SMEM);
    cudaFuncSetAttribute(gemm_bf3, cudaFuncAttributeMaxDynamicSharedMemorySize,
                         GM_SMEM);

    detect_kernel<<<1, 32>>>((const unsigned *)x);

    // layer 0: per-vocab gate table + tensor-core scan
    {
        dim3 gt(G3 / 64, Vq / 128);
        gemm_bf3<<<gt, 256, GM_SMEM>>>(E, Wih, bih, tab, Vq, G3, Dq);
    }
    bar_reset<<<1, GRU_NBLK>>>();
    gru_mma<<<GRU_NBLK, GRU_THREADS, GRU_DYN_SMEM>>>(Whh, bhh, tab, x, act1);

    // layer 1: dense input-gate GEMM (bf16 HMMA) + tensor-core scan
    {
        dim3 gx(G3 / 64, Mq / 128);
        gemm_bf3<<<gx, 256, GM_SMEM>>>(act1, Wih + (size_t)G3 * Dq, bih + G3,
                                       xg, Mq, G3, Dq);
    }
    bar_reset<<<1, GRU_NBLK>>>();
    gru_mma<<<GRU_NBLK, GRU_THREADS, GRU_DYN_SMEM>>>(Whh + (size_t)G3 * Dq,
                                                     bhh + G3, xg, nullptr, act0);

    // LayerNorm + tied head (bf16 HMMA)
    ln_kernel<<<Mq, 256>>>(act0, act1, gamma, beta);
    dim3 gh(Vq / 64, Mq / 128);
    gemm_bf3<<<gh, 256, GM_SMEM>>>(act1, E, nullptr, out, Mq, Vq, Dq);
}

// round 15
// speedup vs baseline: 1.1145x; 1.0041x over previous
#include <cuda_runtime.h>
#include <cuda_bf16.h>
#include <cstdint>
#include <cstddef>

// ---------------------------------------------------------------------------
// Problem constants
// ---------------------------------------------------------------------------
#define Bq   32
#define Tq   512
#define Dq   1024
#define Vq   256
#define Mq   (Bq * Tq)      // 16384 rows
#define G3   (3 * Dq)       // 3072 gate rows

// ---------------------------------------------------------------------------
// Scratch (static device arrays; no allocation allowed)
// ---------------------------------------------------------------------------
__device__ float g_act0[(size_t)Mq * Dq];          // 64 MB
__device__ float g_act1[(size_t)Mq * Dq];          // 64 MB
__device__ float g_xg[(size_t)Mq * G3];            // 192 MB (layer-1 gates)
__device__ float g_tab[(size_t)Vq * G3];           // 3 MB  (layer-0 gate table)
__device__ __nv_bfloat16 g_hhi[2][Bq * Dq];        // bf16 hi of h (dbl-buffered)
__device__ __nv_bfloat16 g_hlo[2][Bq * Dq];        // bf16 lo of h
__device__ int g_x_is64;

// ---------------------------------------------------------------------------
// GRU config: 128 CTAs x (8 dims -> 24 gate rows pad 32) x full K=1024.
// Warp = (rowgroup rg in {0,1}, k-quarter kq in {0..3}).
// ---------------------------------------------------------------------------
#define GRU_NBLK    128
#define GRU_THREADS 256
#define ROWB        2064                 // 1024 bf16 + 8 pad = 2064 B row stride
#define SM_BLO_OFF  (32 * ROWB)          // 66048
#define SM_RED_OFF  (2 * 32 * ROWB)      // 132096
#define GRU_DYN_SMEM (SM_RED_OFF + 4 * 2 * 16 * 32 * 4 + 256)   // ~148.7 KB

// ---------------------------------------------------------------------------
// Barrier state: one arrival slot per CTA, 256B apart (distinct L2 lines).
// Single-writer slots; reset to 0 by bar_reset before each scan launch.
// ---------------------------------------------------------------------------
#define CPAD 64
__device__ unsigned g_slot[GRU_NBLK * CPAD];

// ---------------------------------------------------------------------------
// bf16 HMMA GEMM config (3-pass split): BM=128, BN=64, BK=64, 256 thr
// ---------------------------------------------------------------------------
#define GM_STRIDE  144                   // 64 bf16 = 128 B + 16 pad
#define GM_A_BYTES (128 * GM_STRIDE)     // 18432
#define GM_W_BYTES (64 * GM_STRIDE)      // 9216
#define GM_SMEM    (2 * GM_A_BYTES + 2 * GM_W_BYTES)   // 55296

__device__ __forceinline__ uint32_t smem_u32(const void *p) {
    uint32_t a;
    asm("{ .reg .u64 t; cvta.to.shared.u64 t, %1; cvt.u32.u64 %0, t; }"
        : "=r"(a) : "l"(p));
    return a;
}
__device__ __forceinline__ void ldmx4(uint32_t &r0, uint32_t &r1,
                                      uint32_t &r2, uint32_t &r3, uint32_t addr) {
    asm volatile("ldmatrix.sync.aligned.m8n8.x4.shared.b16 {%0,%1,%2,%3}, [%4];"
                 : "=r"(r0), "=r"(r1), "=r"(r2), "=r"(r3) : "r"(addr));
}
__device__ __forceinline__ void mma_bf16(float &c0, float &c1, float &c2, float &c3,
                                         uint32_t a0, uint32_t a1, uint32_t a2,
                                         uint32_t a3, uint32_t b0, uint32_t b1) {
    asm volatile(
        "mma.sync.aligned.m16n8k16.row.col.f32.bf16.bf16.f32 "
        "{%0,%1,%2,%3}, {%4,%5,%6,%7}, {%8,%9}, {%0,%1,%2,%3};"
        : "+f"(c0), "+f"(c1), "+f"(c2), "+f"(c3)
        : "r"(a0), "r"(a1), "r"(a2), "r"(a3), "r"(b0), "r"(b1));
}
__device__ __forceinline__ void split4(float4 v, uint2 &hi, uint2 &lo) {
    __nv_bfloat16 h0 = __float2bfloat16(v.x);
    __nv_bfloat16 h1 = __float2bfloat16(v.y);
    __nv_bfloat16 h2 = __float2bfloat16(v.z);
    __nv_bfloat16 h3 = __float2bfloat16(v.w);
    union { __nv_bfloat162 b[2]; uint2 u; } H, L;
    H.b[0] = __nv_bfloat162(h0, h1);
    H.b[1] = __nv_bfloat162(h2, h3);
    L.b[0] = __nv_bfloat162(__float2bfloat16(v.x - __bfloat162float(h0)),
                            __float2bfloat16(v.y - __bfloat162float(h1)));
    L.b[1] = __nv_bfloat162(__float2bfloat16(v.z - __bfloat162float(h2)),
                            __float2bfloat16(v.w - __bfloat162float(h3)));
    hi = H.u; lo = L.u;
}

// ---------------------------------------------------------------------------
// Grid barrier v3: one-hop all-to-all. (R11, proven)
// ---------------------------------------------------------------------------
__device__ __forceinline__ void gbar(int blk, int tid, unsigned &gen) {
    gen += 1u;
    __syncthreads();
    if (tid == 0)
        asm volatile("st.release.gpu.global.u32 [%0], %1;"
                     :: "l"(g_slot + blk * CPAD), "r"(gen) : "memory");
    if (tid < GRU_NBLK) {
        unsigned v;
        do {
            asm volatile("ld.acquire.gpu.global.u32 %0, [%1];"
                         : "=r"(v) : "l"(g_slot + tid * CPAD) : "memory");
        } while ((int)(v - gen) < 0);
    }
    __syncthreads();
}

// Stream-ordered slot reset (runs alone before each scan launch).
__global__ void bar_reset() {
    if (threadIdx.x < GRU_NBLK) g_slot[threadIdx.x * CPAD] = 0u;
}

// ---------------------------------------------------------------------------
// int64-vs-int32 token dtype detection
// ---------------------------------------------------------------------------
__global__ void detect_kernel(const unsigned * __restrict__ xw) {
    if (threadIdx.x == 0 && blockIdx.x == 0) {
        int is64 = 1;
        for (int i = 1; i < 128; i += 2)
            if (xw[i] != 0u) { is64 = 0; break; }
        g_x_is64 = is64;
    }
}

// ---------------------------------------------------------------------------
// Split-bf16 (3-pass) HMMA NT GEMM, software-pipelined k-loop (R14, proven).
// ---------------------------------------------------------------------------
__global__ __launch_bounds__(256) void gemm_bf3(const float * __restrict__ A,
                                                const float * __restrict__ W,
                                                const float * __restrict__ bias,
                                                float * __restrict__ C,
                                                int M, int N, int K) {
    extern __shared__ char sm[];
    char *sAhi = sm;
    char *sAlo = sm + GM_A_BYTES;
    char *sWhi = sm + 2 * GM_A_BYTES;
    char *sWlo = sWhi + GM_W_BYTES;
    const uint32_t aHiA = smem_u32(sAhi);
    const uint32_t aLoA = smem_u32(sAlo);
    const uint32_t wHiA = smem_u32(sWhi);
    const uint32_t wLoA = smem_u32(sWlo);

    const int tid = threadIdx.x;
    const int lane = tid & 31;
    const int wid = tid >> 5;
    const int wm = wid & 3;
    const int wn = wid >> 2;
    const int bm = blockIdx.y * 128;
    const int bn = blockIdx.x * 64;

    float acc[2][4][4];
#pragma unroll
    for (int rg = 0; rg < 2; ++rg)
#pragma unroll
        for (int nt = 0; nt < 4; ++nt)
#pragma unroll
            for (int j = 0; j < 4; ++j) acc[rg][nt][j] = 0.f;

    const uint32_t aAddr = aHiA + (uint32_t)(wm * 32 + (lane & 15)) * GM_STRIDE
                         + (uint32_t)(lane >> 4) * 16;
    const uint32_t aLoOff = aLoA - aHiA;
    const int bRow = ((lane >> 4) & 1) * 8 + (lane & 7);
    const int bCol = ((lane >> 3) & 1) * 16;

    const int ar = tid >> 4, ac = (tid & 15) * 4;   // loader row/col pieces

    // prologue: load k0 = 0
    float4 av[8], wv[4];
#pragma unroll
    for (int j = 0; j < 8; ++j)
        av[j] = *(const float4 *)(A + (size_t)(bm + ar + j * 16) * K + ac);
#pragma unroll
    for (int j = 0; j < 4; ++j)
        wv[j] = *(const float4 *)(W + (size_t)(bn + ar + j * 16) * K + ac);

    for (int k0 = 0; k0 < K; k0 += 64) {
        __syncthreads();
#pragma unroll
        for (int j = 0; j < 8; ++j) {
            uint2 hi, lo;
            split4(av[j], hi, lo);
            *(uint2 *)(sAhi + (ar + j * 16) * GM_STRIDE + (ac >> 2) * 8) = hi;
            *(uint2 *)(sAlo + (ar + j * 16) * GM_STRIDE + (ac >> 2) * 8) = lo;
        }
#pragma unroll
        for (int j = 0; j < 4; ++j) {
            uint2 hi, lo;
            split4(wv[j], hi, lo);
            *(uint2 *)(sWhi + (ar + j * 16) * GM_STRIDE + (ac >> 2) * 8) = hi;
            *(uint2 *)(sWlo + (ar + j * 16) * GM_STRIDE + (ac >> 2) * 8) = lo;
        }
        __syncthreads();

        // prefetch next chunk (overlaps the MMA block below)
        if (k0 + 64 < K) {
#pragma unroll
            for (int j = 0; j < 8; ++j)
                av[j] = *(const float4 *)(A + (size_t)(bm + ar + j * 16) * K
                                          + k0 + 64 + ac);
#pragma unroll
            for (int j = 0; j < 4; ++j)
                wv[j] = *(const float4 *)(W + (size_t)(bn + ar + j * 16) * K
                                          + k0 + 64 + ac);
        }

        uint32_t aH[2][4][4], aL[2][4][4];
#pragma unroll
        for (int rg = 0; rg < 2; ++rg)
#pragma unroll
            for (int ks = 0; ks < 4; ++ks) {
                uint32_t ad = aAddr + (uint32_t)(rg * 16 * GM_STRIDE) + ks * 32;
                ldmx4(aH[rg][ks][0], aH[rg][ks][1], aH[rg][ks][2], aH[rg][ks][3], ad);
                ldmx4(aL[rg][ks][0], aL[rg][ks][1], aL[rg][ks][2], aL[rg][ks][3],
                      ad + aLoOff);
            }
#pragma unroll
        for (int ks = 0; ks < 4; ++ks) {
            uint32_t bh[8], bl[8];
#pragma unroll
            for (int pair = 0; pair < 2; ++pair) {
                uint32_t ba = (uint32_t)((wn * 32 + pair * 16 + bRow) * GM_STRIDE)
                            + bCol + ks * 32;
                ldmx4(bh[pair * 4 + 0], bh[pair * 4 + 1],
                      bh[pair * 4 + 2], bh[pair * 4 + 3], wHiA + ba);
                ldmx4(bl[pair * 4 + 0], bl[pair * 4 + 1],
                      bl[pair * 4 + 2], bl[pair * 4 + 3], wLoA + ba);
            }
#pragma unroll
            for (int rg = 0; rg < 2; ++rg)
#pragma unroll
                for (int nt = 0; nt < 4; ++nt) {
                    const int ib = nt * 2;
                    mma_bf16(acc[rg][nt][0], acc[rg][nt][1], acc[rg][nt][2], acc[rg][nt][3],
                             aH[rg][ks][0], aH[rg][ks][1], aH[rg][ks][2], aH[rg][ks][3],
                             bh[ib], bh[ib + 1]);
                    mma_bf16(acc[rg][nt][0], acc[rg][nt][1], acc[rg][nt][2], acc[rg][nt][3],
                             aH[rg][ks][0], aH[rg][ks][1], aH[rg][ks][2], aH[rg][ks][3],
                             bl[ib], bl[ib + 1]);
                    mma_bf16(acc[rg][nt][0], acc[rg][nt][1], acc[rg][nt][2], acc[rg][nt][3],
                             aL[rg][ks][0], aL[rg][ks][1], aL[rg][ks][2], aL[rg][ks][3],
                             bh[ib], bh[ib + 1]);
                }
        }
    }

    float b2x[4], b2y[4];
#pragma unroll
    for (int nt = 0; nt < 4; ++nt) {
        int col = bn + wn * 32 + nt * 8 + (lane & 3) * 2;
        b2x[nt] = bias ? __ldg(bias + col) : 0.f;
        b2y[nt] = bias ? __ldg(bias + col + 1) : 0.f;
    }
#pragma unroll
    for (int rg = 0; rg < 2; ++rg)
#pragma unroll
        for (int nt = 0; nt < 4; ++nt) {
            int row = bm + wm * 32 + rg * 16 + (lane >> 2);
            int col = bn + wn * 32 + nt * 8 + (lane & 3) * 2;
            float2 v0, v1;
            v0.x = acc[rg][nt][0] + b2x[nt];
            v0.y = acc[rg][nt][1] + b2y[nt];
            v1.x = acc[rg][nt][2] + b2x[nt];
            v1.y = acc[rg][nt][3] + b2y[nt];
            *(float2 *)(C + (size_t)row * N + col) = v0;
            *(float2 *)(C + (size_t)(row + 8) * N + col) = v1;
        }
}

// ---------------------------------------------------------------------------
// Persistent GRU scan, one grid barrier per step.
// NEW: quarter-local staging — each warp-pair (rg pair of kq) stages ONLY its
// own 256-wide k-quarter (warp rg stages rows 2j+rg, 512B coalesced), then
// pair-syncs via named barrier (1+kq, 64 threads) and goes straight to MMA.
// Cross-pair convergence happens at the pre-activation __syncthreads.
// ---------------------------------------------------------------------------
__global__ __launch_bounds__(GRU_THREADS, 1) void gru_mma(
        const float * __restrict__ Whh, const float * __restrict__ bhh,
        const float * __restrict__ xgv, const void * __restrict__ tokens,
        float * __restrict__ outp) {
    extern __shared__ char dynsm[];
    uint32_t raw = smem_u32(dynsm);
    uint32_t base = (raw + 127u) & ~127u;
    char *pb = dynsm + (base - raw);
    char *sB_hi = pb;
    char *sB_lo = pb + SM_BLO_OFF;
    float *red = (float *)(pb + SM_RED_OFF);       // [kq*2+rg][16][32]
    const uint32_t sBhiA = base, sBloA = base + SM_BLO_OFF;

    const int tid  = threadIdx.x;
    const int wid  = tid >> 5;
    const int lane = tid & 31;
    const int blk  = blockIdx.x;
    const int d0   = blk * 8;
    const int rg   = wid & 1;
    const int kq   = wid >> 1;

    // ---- prologue: split-bf16 weight fragments into registers ----
    uint32_t aH[16][4], aL[16][4];
    const uint32_t aAddr = sBhiA + (uint32_t)(rg * 16 + (lane & 15)) * ROWB
                         + (uint32_t)(lane >> 4) * 16 + (uint32_t)kq * 512;
#pragma unroll 1
    for (int pass = 0; pass < 2; ++pass) {
        for (int i = tid; i < 32 * 128; i += GRU_THREADS) {
            int row = i >> 7;          // 0..31
            int c = i & 127;           // 16B group (8 bf16)
            union { __nv_bfloat16 h[8]; uint4 u; } v;
            if (row < 24) {
                int g = row >> 3, dd = row & 7;
                const float *src = Whh + (size_t)(g * Dq + d0 + dd) * Dq + c * 8;
                float4 w0 = *(const float4 *)src;
                float4 w1 = *(const float4 *)(src + 4);
                float f[8] = {w0.x, w0.y, w0.z, w0.w, w1.x, w1.y, w1.z, w1.w};
#pragma unroll
                for (int j = 0; j < 8; ++j) {
                    __nv_bfloat16 hi = __float2bfloat16(f[j]);
                    v.h[j] = (pass == 0) ? hi
                           : __float2bfloat16(f[j] - __bfloat162float(hi));
                }
            } else {
                v.u = make_uint4(0u, 0u, 0u, 0u);
            }
            *(uint4 *)(sB_hi + row * ROWB + c * 16) = v.u;
        }
        __syncthreads();
        if (pass == 0) {
#pragma unroll
            for (int ks = 0; ks < 16; ++ks)
                ldmx4(aH[ks][0], aH[ks][1], aH[ks][2], aH[ks][3], aAddr + ks * 32);
        } else {
#pragma unroll
            for (int ks = 0; ks < 16; ++ks)
                ldmx4(aL[ks][0], aL[ks][1], aL[ks][2], aL[ks][3], aAddr + ks * 32);
        }
        __syncthreads();
    }

    // zero both h buffers
    for (int i = blk * GRU_THREADS + tid; i < 2 * Bq * Dq;
         i += GRU_NBLK * GRU_THREADS) {
        ((__nv_bfloat16 *)g_hhi)[i] = __float2bfloat16(0.f);
        ((__nv_bfloat16 *)g_hlo)[i] = __float2bfloat16(0.f);
    }

    unsigned gen = 0;                  // slots zeroed by bar_reset
    gbar(blk, tid, gen);
    const int x64 = g_x_is64;

    // activation constants (thread -> (dd = tid>>5, b = tid&31))
    const int ab = tid & 31;
    const int ad = tid >> 5;
    const int dglob = d0 + ad;
    const float bh_r = __ldg(bhh + dglob);
    const float bh_z = __ldg(bhh + Dq + dglob);
    const float bh_n = __ldg(bhh + 2 * Dq + dglob);
    float hold = 0.f;

    // B ldmatrix lane pieces
    const int bRow = ((lane >> 4) & 1) * 8 + (lane & 7);
    const int bCol = ((lane >> 3) & 1) * 16;
    const uint32_t bBase = (uint32_t)kq * 512 + (uint32_t)bCol;

    for (int t = 0; t < Tq; ++t) {
        const __nv_bfloat16 *hinH = g_hhi[t & 1];
        const __nv_bfloat16 *hinL = g_hlo[t & 1];
        __nv_bfloat16 *houtH = g_hhi[(t + 1) & 1];
        __nv_bfloat16 *houtL = g_hlo[(t + 1) & 1];

        // prefetch input gates early (hidden under staging + MMA)
        float xr, xz, xn;
        {
            size_t xb;
            if (tokens) {
                int tok;
                if (x64) tok = (int)(((const long long *)tokens)[ab * Tq + t]);
                else     tok = ((const int *)tokens)[ab * Tq + t];
                xb = (size_t)tok * G3 + dglob;
            } else {
                xb = ((size_t)ab * Tq + t) * G3 + dglob;
            }
            xr = __ldg(xgv + xb);
            xz = __ldg(xgv + xb + Dq);
            xn = __ldg(xgv + xb + 2 * Dq);
        }

        // ---- quarter-local staging: warp rg stages rows 2j+rg of its own
        //      kq quarter (32 lanes x 16B = 512B contiguous per row) ----
#pragma unroll
        for (int j = 0; j < 16; ++j) {
            const int row = 2 * j + rg;
            const size_t gs = (size_t)row * Dq + kq * 256 + lane * 8;
            uint4 vh = __ldcg((const uint4 *)(hinH + gs));
            uint4 vl = __ldcg((const uint4 *)(hinL + gs));
            char *db = sB_hi + row * ROWB + kq * 512 + lane * 16;
            *(uint4 *)(db) = vh;
            *(uint4 *)(db + SM_BLO_OFF) = vl;
        }
        // pair-local sync: both rg warps of this quarter staged
        asm volatile("bar.sync %0, 64;" :: "r"(1 + kq) : "memory");

        // ---- per-warp 32x32x256 split-bf16 HMMA (3 passes) ----
        float acc[4][4];
#pragma unroll
        for (int nt = 0; nt < 4; ++nt)
#pragma unroll
            for (int j = 0; j < 4; ++j) acc[nt][j] = 0.f;

#pragma unroll
        for (int ks = 0; ks < 16; ++ks) {
            uint32_t bh[8], bl[8];
#pragma unroll
            for (int pair = 0; pair < 2; ++pair) {
                uint32_t ba = (uint32_t)((pair * 16 + bRow) * ROWB) + bBase + ks * 32;
                ldmx4(bh[pair * 4 + 0], bh[pair * 4 + 1],
                      bh[pair * 4 + 2], bh[pair * 4 + 3], sBhiA + ba);
                ldmx4(bl[pair * 4 + 0], bl[pair * 4 + 1],
                      bl[pair * 4 + 2], bl[pair * 4 + 3], sBloA + ba);
            }
#pragma unroll
            for (int nt = 0; nt < 4; ++nt) {
                const int ib = nt * 2;
                mma_bf16(acc[nt][0], acc[nt][1], acc[nt][2], acc[nt][3],
                         aH[ks][0], aH[ks][1], aH[ks][2], aH[ks][3],
                         bh[ib], bh[ib + 1]);
                mma_bf16(acc[nt][0], acc[nt][1], acc[nt][2], acc[nt][3],
                         aH[ks][0], aH[ks][1], aH[ks][2], aH[ks][3],
                         bl[ib], bl[ib + 1]);
                mma_bf16(acc[nt][0], acc[nt][1], acc[nt][2], acc[nt][3],
                         aL[ks][0], aL[ks][1], aL[ks][2], aL[ks][3],
                         bh[ib], bh[ib + 1]);
            }
        }

        // ---- intra-CTA k-reduction staging ----
        {
            float *rb = red + (size_t)((kq * 2 + rg) * 16 + (lane >> 2)) * 32;
#pragma unroll
            for (int nt = 0; nt < 4; ++nt) {
                const int b = nt * 8 + (lane & 3) * 2;
                float2 v0, v1;
                v0.x = acc[nt][0]; v0.y = acc[nt][1];
                v1.x = acc[nt][2]; v1.y = acc[nt][3];
                *(float2 *)(rb + b) = v0;
                *(float2 *)(rb + 8 * 32 + b) = v1;
            }
        }
        __syncthreads();

        // ---- fused activation (one elem per thread) ----
        {
            float hr = 0.f, hz = 0.f, hn = 0.f;
#pragma unroll
            for (int q = 0; q < 4; ++q) {
                hr += red[((q * 2 + 0) * 16 + ad) * 32 + ab];
                hz += red[((q * 2 + 0) * 16 + 8 + ad) * 32 + ab];
                hn += red[((q * 2 + 1) * 16 + ad) * 32 + ab];
            }
            hr += bh_r; hz += bh_z; hn += bh_n;
            float r = 1.f / (1.f + expf(-(xr + hr)));
            float z = 1.f / (1.f + expf(-(xz + hz)));
            float n = tanhf(xn + r * hn);
            float hnew = (1.f - z) * n + z * hold;
            hold = hnew;
            __nv_bfloat16 hh = __float2bfloat16(hnew);
            houtH[ab * Dq + dglob] = hh;
            houtL[ab * Dq + dglob] = __float2bfloat16(hnew - __bfloat162float(hh));
            outp[((size_t)ab * Tq + t) * Dq + dglob] = hnew;
        }
        gbar(blk, tid, gen);
    }
}

// ---------------------------------------------------------------------------
// LayerNorm over last dim (1024), one block per row
// ---------------------------------------------------------------------------
__global__ __launch_bounds__(256) void ln_kernel(const float * __restrict__ in,
                                                 float * __restrict__ outp,
                                                 const float * __restrict__ gamma,
                                                 const float * __restrict__ beta) {
    __shared__ float red[2][8];
    const int row = blockIdx.x;
    const int tid = threadIdx.x;
    float4 x = *(const float4 *)&in[(size_t)row * Dq + tid * 4];
    float s = x.x + x.y + x.z + x.w;
    float q = x.x * x.x + x.y * x.y + x.z * x.z + x.w * x.w;
#pragma unroll
    for (int off = 16; off; off >>= 1) {
        s += __shfl_xor_sync(0xffffffffu, s, off);
        q += __shfl_xor_sync(0xffffffffu, q, off);
    }
    if ((tid & 31) == 0) { red[0][tid >> 5] = s; red[1][tid >> 5] = q; }
    __syncthreads();
    if (tid < 32) {
        float ss = (tid < 8) ? red[0][tid] : 0.f;
        float qq = (tid < 8) ? red[1][tid] : 0.f;
#pragma unroll
        for (int off = 4; off; off >>= 1) {
            ss += __shfl_xor_sync(0xffffffffu, ss, off);
            qq += __shfl_xor_sync(0xffffffffu, qq, off);
        }
        if (tid == 0) { red[0][0] = ss; red[1][0] = qq; }
    }
    __syncthreads();
    const float mean = red[0][0] * (1.f / Dq);
    const float var = red[1][0] * (1.f / Dq) - mean * mean;
    const float inv = rsqrtf(var + 1e-5f);
    float4 g  = *(const float4 *)&gamma[tid * 4];
    float4 be = *(const float4 *)&beta[tid * 4];
    float4 o;
    o.x = (x.x - mean) * inv * g.x + be.x;
    o.y = (x.y - mean) * inv * g.y + be.y;
    o.z = (x.z - mean) * inv * g.z + be.z;
    o.w = (x.w - mean) * inv * g.w + be.w;
    *(float4 *)&outp[(size_t)row * Dq + tid * 4] = o;
}

// ---------------------------------------------------------------------------
// Host driver. Inputs: x, E, Wih, Whh, bih, bhh, gamma, beta. Output f32.
// ---------------------------------------------------------------------------
extern "C" void kernel_launch(void *const *d_in, const int *in_sizes, int n_in,
                              void *d_out, int out_size) {
    (void)in_sizes; (void)n_in; (void)out_size;
    const void  *x     = d_in[0];
    const float *E     = (const float *)d_in[1];
    const float *Wih   = (const float *)d_in[2];
    const float *Whh   = (const float *)d_in[3];
    const float *bih   = (const float *)d_in[4];
    const float *bhh   = (const float *)d_in[5];
    const float *gamma = (const float *)d_in[6];
    const float *beta  = (const float *)d_in[7];
    float *out = (float *)d_out;

    float *act0 = nullptr, *act1 = nullptr, *xg = nullptr, *tab = nullptr;
    cudaGetSymbolAddress((void **)&act0, g_act0);
    cudaGetSymbolAddress((void **)&act1, g_act1);
    cudaGetSymbolAddress((void **)&xg, g_xg);
    cudaGetSymbolAddress((void **)&tab, g_tab);

    cudaFuncSetAttribute(gru_mma, cudaFuncAttributeMaxDynamicSharedMemorySize,
                         GRU_DYN_SMEM);
    cudaFuncSetAttribute(gemm_bf3, cudaFuncAttributeMaxDynamicSharedMemorySize,
                         GM_SMEM);

    detect_kernel<<<1, 32>>>((const unsigned *)x);

    // layer 0: per-vocab gate table + tensor-core scan
    {
        dim3 gt(G3 / 64, Vq / 128);
        gemm_bf3<<<gt, 256, GM_SMEM>>>(E, Wih, bih, tab, Vq, G3, Dq);
    }
    bar_reset<<<1, GRU_NBLK>>>();
    gru_mma<<<GRU_NBLK, GRU_THREADS, GRU_DYN_SMEM>>>(Whh, bhh, tab, x, act1);

    // layer 1: dense input-gate GEMM (bf16 HMMA) + tensor-core scan
    {
        dim3 gx(G3 / 64, Mq / 128);
        gemm_bf3<<<gx, 256, GM_SMEM>>>(act1, Wih + (size_t)G3 * Dq, bih + G3,
                                       xg, Mq, G3, Dq);
    }
    bar_reset<<<1, GRU_NBLK>>>();
    gru_mma<<<GRU_NBLK, GRU_THREADS, GRU_DYN_SMEM>>>(Whh + (size_t)G3 * Dq,
                                                     bhh + G3, xg, nullptr, act0);

    // LayerNorm + tied head (bf16 HMMA)
    ln_kernel<<<Mq, 256>>>(act0, act1, gamma, beta);
    dim3 gh(Vq / 64, Mq / 128);
    gemm_bf3<<<gh, 256, GM_SMEM>>>(act1, E, nullptr, out, Mq, Vq, Dq);
}